// round 14
// baseline (speedup 1.0000x reference)
#include <cuda_runtime.h>
#include <cuda_fp16.h>
#include <math.h>

// Problem constants (fixed by the dataset)
#define NB 4
#define NP 256
#define NC 151
#define NR 51
#define WREL 0.5f
#define NL NC                 // label classes index into [0,151)
#define NK (2*NL*NR)          // 15402 combined contraction dim (d,l,r)
#define NZSTRIDE 15408        // padded to multiple of 8 for unrolled int4 loads
#define NS 8                  // split-k factor in accum
#define MPSTRIDE 152          // padded c-stride for Mp (8B aligned)

// Static scratch (no allocations allowed)
__device__ __half d_Hw[NB * NK * NP];           // [b][k=(d,l,r)][q], WREL-prescaled, fp16 (~31.5 MB)
__device__ float d_thetaPart[NS * NB * NC * NP];// split-k partials [s][b][c][q] (fp32)
__device__ float d_Mp[NL * NR * MPSTRIDE];      // Mp[l][r][c] = M[l,c,r]+M[c,l,r], c contiguous
__device__ int   d_nzk[NC * NZSTRIDE];          // per-c sparse lists over k (r>=1 only)
__device__ int   d_nzcnt[NC];
__device__ int   d_binStart[NB][NL + 1];
__device__ int   d_perm[NB][NP];
__device__ float d_loss[NB * NP];

// NOTE: the c-independent terms (the all-ones r=0 plane of M, both for theta
// and for the diagonal correction D) shift every logit theta[b,q,*] equally
// and cancel exactly in log_softmax -> they are simply omitted everywhere.

// ---------------------------------------------------------------------------
// 1) Per-image label binning (deterministic, stable order)
// ---------------------------------------------------------------------------
__global__ void bin_kernel(const int* __restrict__ labels) {
    int b = blockIdx.x;
    __shared__ int slab[NP];
    __shared__ int scnt[NL];
    __shared__ int soff[NL + 1];
    int t = threadIdx.x;
    if (t < NP) slab[t] = labels[b * NP + t];
    __syncthreads();
    if (t < NL) {
        int c = 0;
        #pragma unroll 8
        for (int i = 0; i < NP; i++) c += (slab[i] == t);
        scnt[t] = c;
    }
    __syncthreads();
    if (t == 0) {
        int acc = 0;
        for (int l = 0; l < NL; l++) { soff[l] = acc; acc += scnt[l]; }
        soff[NL] = acc;
    }
    __syncthreads();
    if (t <= NL) d_binStart[b][t] = soff[t];
    if (t < NL) {
        int o = soff[t];
        for (int i = 0; i < NP; i++)
            if (slab[i] == t) d_perm[b][o++] = i;
    }
}

// ---------------------------------------------------------------------------
// 2) H build, register-accumulated. Block per (l, q-tile(64), d, b).
//    Each thread owns NEL=13 fixed (tq,r) slots in registers. All rows
//    scaled by WREL; output stored fp16 (accumulation was fp32).
// ---------------------------------------------------------------------------
#define TILEQ 64
#define TILE_ELEMS (TILEQ * NR)          // 3264
#define NEL 13                           // ceil(3264/256)

__global__ void hbuild_kernel(const float* __restrict__ rel) {
    int bx = blockIdx.x;
    int l = bx >> 2;
    int q0 = (bx & 3) * TILEQ;
    int d = blockIdx.y, b = blockIdx.z;
    int t = threadIdx.x;

    __shared__ float s[TILEQ * 53];      // pad 53 (odd) -> conflict-free transpose

    int start = d_binStart[b][l];
    int end   = d_binStart[b][l + 1];

    float reg[NEL];
    #pragma unroll
    for (int j = 0; j < NEL; j++) reg[j] = 0.0f;

    if (d == 0) {
        // out[tq][r] = sum_m rel[b, p_m, q0+tq, r] : contiguous 3264-elem slab per m
        const float* relb = rel + (size_t)b * NP * NP * NR + q0 * NR;
        for (int m = start; m < end; m++) {
            int p = d_perm[b][m];
            const float* base = relb + p * (NP * NR);
            #pragma unroll
            for (int j = 0; j < NEL; j++) {
                int idx = t + j * 256;
                if (idx < TILE_ELEMS) reg[j] += __ldg(base + idx);
            }
        }
    } else {
        // out[tq][r] = sum_m rel[b, q0+tq, p_m, r] : int offsets from one base
        int off[NEL];
        #pragma unroll
        for (int j = 0; j < NEL; j++) {
            int idx = t + j * 256;
            int tq = idx / NR, r = idx - tq * NR;
            off[j] = tq * (NP * NR) + r;
        }
        const float* relb = rel + (size_t)(b * NP + q0) * NP * NR;
        for (int m = start; m < end; m++) {
            int po = d_perm[b][m] * NR;
            #pragma unroll
            for (int j = 0; j < NEL; j++) {
                int idx = t + j * 256;
                if (idx < TILE_ELEMS) reg[j] += __ldg(relb + off[j] + po);
            }
        }
    }

    // Stage to smem in (tq, r) order
    #pragma unroll
    for (int j = 0; j < NEL; j++) {
        int idx = t + j * 256;
        if (idx < TILE_ELEMS) {
            int tq = idx / NR, r = idx - tq * NR;
            s[tq * 53 + r] = reg[j];
        }
    }
    __syncthreads();

    // Write transposed fp16: Hw[b][d][l][r][q0+tq], uniform WREL scale.
    __half* out = d_Hw + (size_t)(((b * 2 + d) * NL + l) * NR) * NP + q0;
    for (int idx = t; idx < NR * TILEQ; idx += 256) {
        int r = idx >> 6, tq = idx & 63;
        out[r * NP + tq] = __float2half_rn(WREL * s[tq * 53 + r]);
    }
}

// ---------------------------------------------------------------------------
// 3) Sparse list build per c, r>=1 only. Ballot compaction -> ascending-k
//    deterministic order.
// ---------------------------------------------------------------------------
__global__ void listbuild_kernel(const float* __restrict__ M) {
    int c = blockIdx.x;
    int lane = threadIdx.x;
    int cnt = 0;
    int* list = d_nzk + c * NZSTRIDE;
    for (int base = 0; base < NK; base += 32) {
        int k = base + lane;
        float v = 0.0f;
        if (k < NK) {
            int d = k / (NL * NR);
            int lr = k - d * NL * NR;
            int l = lr / NR, r = lr - l * NR;
            if (r != 0)
                v = (d == 0) ? M[((size_t)l * NC + c) * NR + r]
                             : M[((size_t)c * NC + l) * NR + r];
        }
        unsigned mask = __ballot_sync(0xFFFFFFFFu, v != 0.0f);
        if (v != 0.0f) {
            int pos = cnt + __popc(mask & ((1u << lane) - 1u));
            list[pos] = k;
        }
        cnt += __popc(mask);
    }
    if (lane == 0) d_nzcnt[c] = cnt;
}

// ---------------------------------------------------------------------------
// 3b) Mp[l][r][c] = M[l,c,r] + M[c,l,r], c contiguous -> loss reads coalesced.
//     M[l] slab staged in smem (coalesced); the transpose term is gathered
//     once here instead of 1024 times in loss.
// ---------------------------------------------------------------------------
__global__ void mp_kernel(const float* __restrict__ M) {
    int l = blockIdx.x;
    __shared__ float sM[NC * NR];        // M[l, :, :], 30.8 KB
    for (int i = threadIdx.x; i < NC * NR; i += 256)
        sM[i] = M[(size_t)l * NC * NR + i];
    __syncthreads();
    for (int i = threadIdx.x; i < (NR - 1) * NC; i += 256) {
        int r = i / NC + 1, c = i - (r - 1) * NC;
        d_Mp[((size_t)l * NR + r) * MPSTRIDE + c] =
            sM[c * NR + r] + __ldg(&M[((size_t)c * NC + l) * NR + r]);
    }
}

// ---------------------------------------------------------------------------
// 4) Sparse accumulate, split-k, fp16 rows: part[s][b][c][q] = sum over
//    k-chunk s of Hw[b][k][q]. warp = one c, lane = 4 consecutive q
//    (loaded as float2 = 4 halves), fp32 accumulation, 8-deep unroll.
// ---------------------------------------------------------------------------
__device__ __forceinline__ float4 ldH4(const float2* p) {
    float2 v = __ldg(p);
    float2 fa = __half22float2(*reinterpret_cast<__half2*>(&v.x));
    float2 fb = __half22float2(*reinterpret_cast<__half2*>(&v.y));
    return make_float4(fa.x, fa.y, fb.x, fb.y);
}

__global__ void accum_kernel() {
    int warp = threadIdx.x >> 5, lane = threadIdx.x & 31;
    int c = blockIdx.x * 8 + warp;
    int q4 = blockIdx.y * 32 + lane;          // 4-half group index; q = 4*q4
    int bs = blockIdx.z;
    int b = bs & 3, s = bs >> 2;
    if (c >= NC) return;
    const float2* H = (const float2*)(d_Hw + (size_t)b * NK * NP) + q4;
    const int* list = d_nzk + c * NZSTRIDE;
    int n = d_nzcnt[c];
    int i0 = ((n * s / NS) >> 2) << 2;
    int i1 = (s == NS - 1) ? n : ((n * (s + 1) / NS) >> 2) << 2;
    float4 a0 = make_float4(0.f, 0.f, 0.f, 0.f), a1 = a0, a2 = a0, a3 = a0;
    int i = i0;
    for (; i + 8 <= i1; i += 8) {
        int4 ka = *(const int4*)(list + i);
        int4 kb = *(const int4*)(list + i + 4);
        float4 v0 = ldH4(H + ka.x * (NP / 4));
        float4 v1 = ldH4(H + ka.y * (NP / 4));
        float4 v2 = ldH4(H + ka.z * (NP / 4));
        float4 v3 = ldH4(H + ka.w * (NP / 4));
        float4 v4 = ldH4(H + kb.x * (NP / 4));
        float4 v5 = ldH4(H + kb.y * (NP / 4));
        float4 v6 = ldH4(H + kb.z * (NP / 4));
        float4 v7 = ldH4(H + kb.w * (NP / 4));
        a0.x += v0.x; a0.y += v0.y; a0.z += v0.z; a0.w += v0.w;
        a1.x += v1.x; a1.y += v1.y; a1.z += v1.z; a1.w += v1.w;
        a2.x += v2.x; a2.y += v2.y; a2.z += v2.z; a2.w += v2.w;
        a3.x += v3.x; a3.y += v3.y; a3.z += v3.z; a3.w += v3.w;
        a0.x += v4.x; a0.y += v4.y; a0.z += v4.z; a0.w += v4.w;
        a1.x += v5.x; a1.y += v5.y; a1.z += v5.z; a1.w += v5.w;
        a2.x += v6.x; a2.y += v6.y; a2.z += v6.z; a2.w += v6.w;
        a3.x += v7.x; a3.y += v7.y; a3.z += v7.z; a3.w += v7.w;
    }
    for (; i < i1; i++) {
        float4 v = ldH4(H + list[i] * (NP / 4));
        a0.x += v.x; a0.y += v.y; a0.z += v.z; a0.w += v.w;
    }
    float4 r;
    r.x = a0.x + a1.x + a2.x + a3.x;
    r.y = a0.y + a1.y + a2.y + a3.y;
    r.z = a0.z + a1.z + a2.z + a3.z;
    r.w = a0.w + a1.w + a2.w + a3.w;
    float4* T = (float4*)(d_thetaPart + ((size_t)(s * NB + b) * NC + c) * NP) + q4;
    *T = r;
}

// ---------------------------------------------------------------------------
// 5) Loss: per (b,q) block. Combines split-k partials (fixed s order) and
//    diagonal correction (r>=1, coalesced via Mp), then log-softmax over c.
//    theta = 0.5*part - 0.5*D  (c-uniform terms dropped: softmax-invariant)
// ---------------------------------------------------------------------------
__global__ void loss_kernel(const float* __restrict__ rel,
                            const int* __restrict__ labels) {
    int q = blockIdx.x, b = blockIdx.y;
    int c = threadIdx.x;
    __shared__ float sw[NR];             // WREL * rel_diag[r] (r>=1 used)
    __shared__ int slab;
    __shared__ float red[256];
    if (threadIdx.x == 0) slab = labels[b * NP + q];
    if (threadIdx.x < NR)
        sw[threadIdx.x] = WREL * rel[((size_t)(b * NP + q) * NP + q) * NR + threadIdx.x];
    __syncthreads();
    int lab = slab;
    float t = -INFINITY;
    if (c < NC) {
        const float* mp = d_Mp + (size_t)lab * NR * MPSTRIDE + c;
        float D = 0.0f;
        #pragma unroll
        for (int r = 1; r < NR; r++)
            D += sw[r] * __ldg(mp + r * MPSTRIDE);
        float part = 0.0f;
        #pragma unroll
        for (int s = 0; s < NS; s++)
            part += d_thetaPart[((size_t)(s * NB + b) * NC + c) * NP + q];
        t = 0.5f * (part - D);
    }
    red[threadIdx.x] = t;
    __syncthreads();
    for (int s = 128; s > 0; s >>= 1) {
        if (threadIdx.x < s) red[threadIdx.x] = fmaxf(red[threadIdx.x], red[threadIdx.x + s]);
        __syncthreads();
    }
    float mx = red[0];
    __syncthreads();
    float e = (c < NC) ? expf(t - mx) : 0.0f;
    red[threadIdx.x] = e;
    __syncthreads();
    for (int s = 128; s > 0; s >>= 1) {
        if (threadIdx.x < s) red[threadIdx.x] += red[threadIdx.x + s];
        __syncthreads();
    }
    float lse = mx + logf(red[0]);
    if (c == lab) d_loss[b * NP + q] = lse - t;
}

// ---------------------------------------------------------------------------
// 6) Mean over 1024 losses -> scalar output (fixed-order reduction)
// ---------------------------------------------------------------------------
__global__ void mean_kernel(float* __restrict__ out) {
    __shared__ float red[256];
    int t = threadIdx.x;
    float v = d_loss[t] + d_loss[t + 256] + d_loss[t + 512] + d_loss[t + 768];
    red[t] = v;
    __syncthreads();
    for (int s = 128; s > 0; s >>= 1) {
        if (t < s) red[t] += red[t + s];
        __syncthreads();
    }
    if (t == 0) out[0] = red[0] * (1.0f / (NB * NP));
}

// ---------------------------------------------------------------------------
extern "C" void kernel_launch(void* const* d_in, const int* in_sizes, int n_in,
                              void* d_out, int out_size) {
    // inputs: 0=roi_scores (unused: _unary is dead code in the reference),
    //         1=rel_scores, 2=relationship_mat, 3=roi_labels, 4=num_images
    const float* rel    = (const float*)d_in[1];
    const float* M      = (const float*)d_in[2];
    const int*   labels = (const int*)d_in[3];
    float* out = (float*)d_out;

    bin_kernel<<<NB, 256>>>(labels);
    listbuild_kernel<<<NC, 32>>>(M);
    mp_kernel<<<NL, 256>>>(M);
    hbuild_kernel<<<dim3(NL * 4, 2, NB), 256>>>(rel);
    accum_kernel<<<dim3((NC + 7) / 8, NP / 128, NB * NS), 256>>>();
    loss_kernel<<<dim3(NP, NB), 256>>>(rel, labels);
    mean_kernel<<<1, 256>>>(out);
}

// round 16
// speedup vs baseline: 2.7583x; 2.7583x over previous
#include <cuda_runtime.h>
#include <cuda_fp16.h>
#include <math.h>

// Problem constants (fixed by the dataset)
#define NB 4
#define NP 256
#define NC 151
#define NR 51
#define WREL 0.5f
#define NL NC                 // label classes index into [0,151)
#define NK (2*NL*NR)          // 15402 combined contraction dim (d,l,r)
#define NZSTRIDE 15408        // padded to multiple of 8 for unrolled int4 loads
#define NS 8                  // split-k factor in accum
#define MPSTRIDE 152          // padded c-stride for Mp (8B aligned)

// listbuild two-phase geometry: 8 warps x 61 iters x 32 lanes >= NK
#define LB_WARPS 8
#define LB_ITER 61
#define LB_CHUNK (LB_ITER * 32)   // 1952 k's per warp

// Static scratch (no allocations allowed)
__device__ __half d_Hw[NB * NK * NP];           // [b][k=(d,l,r)][q], WREL-prescaled, fp16 (~31.5 MB)
__device__ float d_thetaPart[NS * NB * NC * NP];// split-k partials [s][b][c][q] (fp32)
__device__ float d_Mp[NL * NR * MPSTRIDE];      // Mp[l][r][c] = M[l,c,r]+M[c,l,r], c contiguous
__device__ int   d_nzk[NC * NZSTRIDE];          // per-c sparse lists over k (r>=1 only)
__device__ int   d_nzcnt[NC];
__device__ int   d_binStart[NB][NL + 1];
__device__ int   d_perm[NB][NP];
__device__ float d_loss[NB * NP];

// NOTE: the c-independent terms (the all-ones r=0 plane of M, both for theta
// and for the diagonal correction D) shift every logit theta[b,q,*] equally
// and cancel exactly in log_softmax -> they are simply omitted everywhere.

// ---------------------------------------------------------------------------
// 1) Fused prep kernel, dispatched on blockIdx.x:
//    [0, NB)            : per-image label binning (stable order)
//    [NB, NB+NC)        : sparse list build for c (8-warp two-phase)
//    [NB+NC, NB+NC+NL)  : Mp build for l
// ---------------------------------------------------------------------------
__global__ void prep_kernel(const float* __restrict__ M,
                            const int* __restrict__ labels) {
    __shared__ __align__(16) char sbuf[NC * NR * 4 + 64];   // 30.9 KB, unioned
    int bid = blockIdx.x;
    int t = threadIdx.x;

    if (bid < NB) {
        // ---- binning ----
        int b = bid;
        int* slab = (int*)sbuf;                  // [NP]
        int* scnt = slab + NP;                   // [NL]
        int* soff = scnt + NL;                   // [NL+1]
        if (t < NP) slab[t] = labels[b * NP + t];
        __syncthreads();
        if (t < NL) {
            int c = 0;
            #pragma unroll 8
            for (int i = 0; i < NP; i++) c += (slab[i] == t);
            scnt[t] = c;
        }
        __syncthreads();
        if (t == 0) {
            int acc = 0;
            for (int l = 0; l < NL; l++) { soff[l] = acc; acc += scnt[l]; }
            soff[NL] = acc;
        }
        __syncthreads();
        if (t <= NL) d_binStart[b][t] = soff[t];
        if (t < NL) {
            int o = soff[t];
            for (int i = 0; i < NP; i++)
                if (slab[i] == t) d_perm[b][o++] = i;
        }
    } else if (bid < NB + NC) {
        // ---- list build for one c: phase1 masks+counts, scan, phase2 emit ----
        int c = bid - NB;
        unsigned* masks = (unsigned*)sbuf;                    // [LB_WARPS][LB_ITER]
        int* wcnt = (int*)(sbuf + LB_WARPS * LB_ITER * 4);    // [LB_WARPS]
        int w = t >> 5, lane = t & 31;
        int kbase = w * LB_CHUNK + lane;
        int cnt = 0;
        #pragma unroll 4
        for (int it = 0; it < LB_ITER; it++) {
            int k = kbase + it * 32;
            float v = 0.0f;
            if (k < NK) {
                int d = (k >= NL * NR) ? 1 : 0;
                int lr = k - d * (NL * NR);
                int l = lr / NR, r = lr - l * NR;
                if (r != 0)
                    v = (d == 0) ? __ldg(&M[(l * NC + c) * NR + r])
                                 : __ldg(&M[(c * NC + l) * NR + r]);
            }
            unsigned m = __ballot_sync(0xFFFFFFFFu, v != 0.0f);
            if (lane == 0) masks[w * LB_ITER + it] = m;
            cnt += __popc(m);
        }
        if (lane == 0) wcnt[w] = cnt;
        __syncthreads();
        if (t == 0) {
            int a = 0;
            for (int i = 0; i < LB_WARPS; i++) { int x = wcnt[i]; wcnt[i] = a; a += x; }
            d_nzcnt[c] = a;
        }
        __syncthreads();
        int off = wcnt[w];
        int* list = d_nzk + c * NZSTRIDE;
        for (int it = 0; it < LB_ITER; it++) {
            unsigned m = masks[w * LB_ITER + it];
            if (m & (1u << lane)) {
                int pos = off + __popc(m & ((1u << lane) - 1u));
                list[pos] = kbase + it * 32;
            }
            off += __popc(m);
        }
    } else {
        // ---- Mp[l][r][c] = M[l,c,r] + M[c,l,r], c contiguous ----
        int l = bid - NB - NC;
        float* sM = (float*)sbuf;                // M[l, :, :], 30.8 KB
        for (int i = t; i < NC * NR; i += 256)
            sM[i] = M[(size_t)l * NC * NR + i];
        __syncthreads();
        #pragma unroll 4
        for (int i = t; i < (NR - 1) * NC; i += 256) {
            int r = i / NC + 1, c = i - (r - 1) * NC;
            d_Mp[((size_t)l * NR + r) * MPSTRIDE + c] =
                sM[c * NR + r] + __ldg(&M[((size_t)c * NC + l) * NR + r]);
        }
    }
}

// ---------------------------------------------------------------------------
// 2) H build, register-accumulated. Block per (l, q-tile(64), d, b).
//    Each thread owns NEL=13 fixed (tq,r) slots in registers. All rows
//    scaled by WREL; output stored fp16 (accumulation in fp32).
// ---------------------------------------------------------------------------
#define TILEQ 64
#define TILE_ELEMS (TILEQ * NR)          // 3264
#define NEL 13                           // ceil(3264/256)

__global__ void hbuild_kernel(const float* __restrict__ rel) {
    int bx = blockIdx.x;
    int l = bx >> 2;
    int q0 = (bx & 3) * TILEQ;
    int d = blockIdx.y, b = blockIdx.z;
    int t = threadIdx.x;

    __shared__ float s[TILEQ * 53];      // pad 53 (odd) -> conflict-free transpose

    int start = d_binStart[b][l];
    int end   = d_binStart[b][l + 1];

    float reg[NEL];
    #pragma unroll
    for (int j = 0; j < NEL; j++) reg[j] = 0.0f;

    if (d == 0) {
        // out[tq][r] = sum_m rel[b, p_m, q0+tq, r] : contiguous 3264-elem slab per m
        const float* relb = rel + (size_t)b * NP * NP * NR + q0 * NR;
        for (int m = start; m < end; m++) {
            int p = d_perm[b][m];
            const float* base = relb + p * (NP * NR);
            #pragma unroll
            for (int j = 0; j < NEL; j++) {
                int idx = t + j * 256;
                if (idx < TILE_ELEMS) reg[j] += __ldg(base + idx);
            }
        }
    } else {
        // out[tq][r] = sum_m rel[b, q0+tq, p_m, r] : int offsets from one base
        int off[NEL];
        #pragma unroll
        for (int j = 0; j < NEL; j++) {
            int idx = t + j * 256;
            int tq = idx / NR, r = idx - tq * NR;
            off[j] = tq * (NP * NR) + r;
        }
        const float* relb = rel + (size_t)(b * NP + q0) * NP * NR;
        for (int m = start; m < end; m++) {
            int po = d_perm[b][m] * NR;
            #pragma unroll
            for (int j = 0; j < NEL; j++) {
                int idx = t + j * 256;
                if (idx < TILE_ELEMS) reg[j] += __ldg(relb + off[j] + po);
            }
        }
    }

    // Stage to smem in (tq, r) order
    #pragma unroll
    for (int j = 0; j < NEL; j++) {
        int idx = t + j * 256;
        if (idx < TILE_ELEMS) {
            int tq = idx / NR, r = idx - tq * NR;
            s[tq * 53 + r] = reg[j];
        }
    }
    __syncthreads();

    // Write transposed fp16: Hw[b][d][l][r][q0+tq], uniform WREL scale.
    __half* out = d_Hw + (size_t)(((b * 2 + d) * NL + l) * NR) * NP + q0;
    for (int idx = t; idx < NR * TILEQ; idx += 256) {
        int r = idx >> 6, tq = idx & 63;
        out[r * NP + tq] = __float2half_rn(WREL * s[tq * 53 + r]);
    }
}

// ---------------------------------------------------------------------------
// 3) Sparse accumulate, split-k, fp16 rows: part[s][b][c][q] = sum over
//    k-chunk s of Hw[b][k][q]. warp = one c, lane = 4 consecutive q
//    (loaded as float2 = 4 halves), fp32 accumulation, 8-deep unroll.
// ---------------------------------------------------------------------------
__device__ __forceinline__ float4 ldH4(const float2* p) {
    float2 v = __ldg(p);
    float2 fa = __half22float2(*reinterpret_cast<__half2*>(&v.x));
    float2 fb = __half22float2(*reinterpret_cast<__half2*>(&v.y));
    return make_float4(fa.x, fa.y, fb.x, fb.y);
}

__global__ void accum_kernel() {
    int warp = threadIdx.x >> 5, lane = threadIdx.x & 31;
    int c = blockIdx.x * 8 + warp;
    int q4 = blockIdx.y * 32 + lane;          // 4-half group index; q = 4*q4
    int bs = blockIdx.z;
    int b = bs & 3, s = bs >> 2;
    if (c >= NC) return;
    const float2* H = (const float2*)(d_Hw + (size_t)b * NK * NP) + q4;
    const int* list = d_nzk + c * NZSTRIDE;
    int n = d_nzcnt[c];
    int i0 = ((n * s / NS) >> 2) << 2;
    int i1 = (s == NS - 1) ? n : ((n * (s + 1) / NS) >> 2) << 2;
    float4 a0 = make_float4(0.f, 0.f, 0.f, 0.f), a1 = a0, a2 = a0, a3 = a0;
    int i = i0;
    for (; i + 8 <= i1; i += 8) {
        int4 ka = *(const int4*)(list + i);
        int4 kb = *(const int4*)(list + i + 4);
        float4 v0 = ldH4(H + ka.x * (NP / 4));
        float4 v1 = ldH4(H + ka.y * (NP / 4));
        float4 v2 = ldH4(H + ka.z * (NP / 4));
        float4 v3 = ldH4(H + ka.w * (NP / 4));
        float4 v4 = ldH4(H + kb.x * (NP / 4));
        float4 v5 = ldH4(H + kb.y * (NP / 4));
        float4 v6 = ldH4(H + kb.z * (NP / 4));
        float4 v7 = ldH4(H + kb.w * (NP / 4));
        a0.x += v0.x; a0.y += v0.y; a0.z += v0.z; a0.w += v0.w;
        a1.x += v1.x; a1.y += v1.y; a1.z += v1.z; a1.w += v1.w;
        a2.x += v2.x; a2.y += v2.y; a2.z += v2.z; a2.w += v2.w;
        a3.x += v3.x; a3.y += v3.y; a3.z += v3.z; a3.w += v3.w;
        a0.x += v4.x; a0.y += v4.y; a0.z += v4.z; a0.w += v4.w;
        a1.x += v5.x; a1.y += v5.y; a1.z += v5.z; a1.w += v5.w;
        a2.x += v6.x; a2.y += v6.y; a2.z += v6.z; a2.w += v6.w;
        a3.x += v7.x; a3.y += v7.y; a3.z += v7.z; a3.w += v7.w;
    }
    for (; i < i1; i++) {
        float4 v = ldH4(H + list[i] * (NP / 4));
        a0.x += v.x; a0.y += v.y; a0.z += v.z; a0.w += v.w;
    }
    float4 r;
    r.x = a0.x + a1.x + a2.x + a3.x;
    r.y = a0.y + a1.y + a2.y + a3.y;
    r.z = a0.z + a1.z + a2.z + a3.z;
    r.w = a0.w + a1.w + a2.w + a3.w;
    float4* T = (float4*)(d_thetaPart + ((size_t)(s * NB + b) * NC + c) * NP) + q4;
    *T = r;
}

// ---------------------------------------------------------------------------
// 4) Loss: per (b,q) block. Combines split-k partials (fixed s order) and
//    diagonal correction (r>=1, coalesced via Mp), then log-softmax over c.
//    theta = 0.5*part - 0.5*D  (c-uniform terms dropped: softmax-invariant)
// ---------------------------------------------------------------------------
__global__ void loss_kernel(const float* __restrict__ rel,
                            const int* __restrict__ labels) {
    int q = blockIdx.x, b = blockIdx.y;
    int c = threadIdx.x;
    __shared__ float sw[NR];             // WREL * rel_diag[r] (r>=1 used)
    __shared__ int slab;
    __shared__ float red[256];
    if (threadIdx.x == 0) slab = labels[b * NP + q];
    if (threadIdx.x < NR)
        sw[threadIdx.x] = WREL * rel[((size_t)(b * NP + q) * NP + q) * NR + threadIdx.x];
    __syncthreads();
    int lab = slab;
    float t = -INFINITY;
    if (c < NC) {
        const float* mp = d_Mp + (size_t)lab * NR * MPSTRIDE + c;
        float D = 0.0f;
        #pragma unroll
        for (int r = 1; r < NR; r++)
            D += sw[r] * __ldg(mp + r * MPSTRIDE);
        float part = 0.0f;
        #pragma unroll
        for (int s = 0; s < NS; s++)
            part += d_thetaPart[((size_t)(s * NB + b) * NC + c) * NP + q];
        t = 0.5f * (part - D);
    }
    red[threadIdx.x] = t;
    __syncthreads();
    for (int s = 128; s > 0; s >>= 1) {
        if (threadIdx.x < s) red[threadIdx.x] = fmaxf(red[threadIdx.x], red[threadIdx.x + s]);
        __syncthreads();
    }
    float mx = red[0];
    __syncthreads();
    float e = (c < NC) ? expf(t - mx) : 0.0f;
    red[threadIdx.x] = e;
    __syncthreads();
    for (int s = 128; s > 0; s >>= 1) {
        if (threadIdx.x < s) red[threadIdx.x] += red[threadIdx.x + s];
        __syncthreads();
    }
    float lse = mx + logf(red[0]);
    if (c == lab) d_loss[b * NP + q] = lse - t;
}

// ---------------------------------------------------------------------------
// 5) Mean over 1024 losses -> scalar output (fixed-order reduction)
// ---------------------------------------------------------------------------
__global__ void mean_kernel(float* __restrict__ out) {
    __shared__ float red[256];
    int t = threadIdx.x;
    float v = d_loss[t] + d_loss[t + 256] + d_loss[t + 512] + d_loss[t + 768];
    red[t] = v;
    __syncthreads();
    for (int s = 128; s > 0; s >>= 1) {
        if (t < s) red[t] += red[t + s];
        __syncthreads();
    }
    if (t == 0) out[0] = red[0] * (1.0f / (NB * NP));
}

// ---------------------------------------------------------------------------
extern "C" void kernel_launch(void* const* d_in, const int* in_sizes, int n_in,
                              void* d_out, int out_size) {
    // inputs: 0=roi_scores (unused: _unary is dead code in the reference),
    //         1=rel_scores, 2=relationship_mat, 3=roi_labels, 4=num_images
    const float* rel    = (const float*)d_in[1];
    const float* M      = (const float*)d_in[2];
    const int*   labels = (const int*)d_in[3];
    float* out = (float*)d_out;

    prep_kernel<<<NB + NC + NL, 256>>>(M, labels);
    hbuild_kernel<<<dim3(NL * 4, 2, NB), 256>>>(rel);
    accum_kernel<<<dim3((NC + 7) / 8, NP / 128, NB * NS), 256>>>();
    loss_kernel<<<dim3(NP, NB), 256>>>(rel, labels);
    mean_kernel<<<1, 256>>>(out);
}